// round 8
// baseline (speedup 1.0000x reference)
#include <cuda_runtime.h>
#include <cuda_bf16.h>
#include <cstdint>

// Problem constants
#define VOCAB      100000
#define EMBED      128
#define BATCH      64
#define SEQLEN     2048
#define NCHUNK     16
#define CHUNK      (SEQLEN / NCHUNK)    // 128 tokens per block
#define STAGE_ROWS 16                   // rows per pipeline stage
#define NSTAGES    (CHUNK / STAGE_ROWS) // 8
#define RING       4                    // ring buffers; prefetch distance 3
                                        // (RING > distance: no live-slot overwrite)

// Device scratch (zero-initialized at load; every execution restores the
// all-zero invariant, so graph replays are deterministic).
__device__ float g_sums[BATCH * EMBED];
__device__ int   g_count[BATCH];

// ---- cp.async helpers -------------------------------------------------------
__device__ __forceinline__ void cp_async16(uint32_t smem_dst, const void* gmem_src) {
    asm volatile("cp.async.cg.shared.global [%0], [%1], 16;"
                 :: "r"(smem_dst), "l"(gmem_src) : "memory");
}
__device__ __forceinline__ void cp_commit() {
    asm volatile("cp.async.commit_group;" ::: "memory");
}
template <int N>
__device__ __forceinline__ void cp_wait() {
    asm volatile("cp.async.wait_group %0;" :: "n"(N) : "memory");
}

// ---------------------------------------------------------------------------
// Single fused kernel. grid = (NCHUNK, BATCH) = (16, 64) = 1024 blocks x 128.
//
// Gather issued through cp.async (LDGSTS): no per-miss register/scoreboard
// cost and no observed outstanding-depth cap, bypassing the ~18-miss/SM LDG
// ceiling measured in R5/R6. Each thread async-copies exactly the 16B chunks
// it later reads back from shared (same rows, same column c), so the pipeline
// needs NO barriers — per-thread cp.async.wait_group is the only ordering.
//
// R7 bug fixed here: with RING=3 the prefetch (distance 3) overwrote the slot
// being consumed in the same iteration. RING=4 keeps the written slot (=slot
// consumed last iteration) disjoint from the slot being read.
// ---------------------------------------------------------------------------
__global__ __launch_bounds__(128) void cbow_fused_kernel(
    const void* __restrict__ xraw,     // [BATCH, SEQLEN] token ids (int64 or int32)
    const float* __restrict__ emb,     // [VOCAB, EMBED] f32
    float* __restrict__ out)           // [BATCH, 4, EMBED] f32
{
    __shared__ int    toks[CHUNK];
    __shared__ float4 buf[RING][STAGE_ROWS][32];   // 32 KB ring
    __shared__ float4 part[128];
    __shared__ int    s_is64;
    __shared__ int    s_last;

    const int b    = blockIdx.y;
    const int base = blockIdx.x * CHUNK;
    const int tid  = threadIdx.x;
    const int c    = tid & 31;   // float4 column of the 128-float row
    const int g    = tid >> 5;   // row phase (0..3)

    // ---- Phase 0: dtype detection (warp 0; first 256B safe under both) ----
    if (tid < 32) {
        const long long v = ((const long long*)xraw)[tid];
        const unsigned bad = __ballot_sync(0xFFFFFFFFu, v < 0 || v >= VOCAB);
        if (tid == 0) s_is64 = (bad == 0u);
    }
    __syncthreads();
    const int is64 = s_is64;

    // ---- Phase 1: stage this chunk's 128 token ids (clamped int32) ----
    {
        const int idx = b * SEQLEN + base + tid;
        long long v = is64 ? ((const long long*)xraw)[idx]
                           : (long long)((const int*)xraw)[idx];
        if (v < 0) v = 0;
        if (v >= VOCAB) v = VOCAB - 1;
        toks[tid] = (int)v;
    }
    __syncthreads();

    // ---- Phase 2: cp.async pipelined gather-accumulate ----
    // Thread (g, c) owns rows {g, g+4, g+8, g+12} of each 16-row stage,
    // bytes [c*16, c*16+16) of each 512B row.
    const uint32_t buf_base = (uint32_t)__cvta_generic_to_shared(&buf[0][0][0]);

    auto issue_stage = [&](int s) {
        const int slot  = s & (RING - 1);
        const int rbase = s * STAGE_ROWS;
        #pragma unroll
        for (int j = 0; j < STAGE_ROWS / 4; j++) {
            const int r   = j * 4 + g;
            const int tok = toks[rbase + r];
            const void* src = (const char*)emb + ((size_t)tok * EMBED + c * 4) * 4;
            const uint32_t dst = buf_base +
                ((uint32_t)(slot * STAGE_ROWS + r) * 32u + (uint32_t)c) * 16u;
            cp_async16(dst, src);
        }
        cp_commit();
    };

    float4 acc = make_float4(0.f, 0.f, 0.f, 0.f);

    issue_stage(0);
    issue_stage(1);
    issue_stage(2);

    #pragma unroll
    for (int s = 0; s < NSTAGES; s++) {
        // Prefetch stage s+3 into slot (s+3)%4 == (s-1)%4 (consumed last iter).
        if (s + 3 < NSTAGES) issue_stage(s + 3);

        // Wait until stage s's group retired. Groups issued so far =
        // min(s+4, NSTAGES); allowed pending = min(3, NSTAGES-1-s).
        if      (s <= NSTAGES - 4) cp_wait<3>();
        else if (s == NSTAGES - 3) cp_wait<2>();
        else if (s == NSTAGES - 2) cp_wait<1>();
        else                       cp_wait<0>();

        const int slot = s & (RING - 1);
        #pragma unroll
        for (int j = 0; j < STAGE_ROWS / 4; j++) {
            const float4 v = buf[slot][j * 4 + g][c];
            acc.x += v.x; acc.y += v.y; acc.z += v.z; acc.w += v.w;
        }
    }

    part[tid] = acc;
    __syncthreads();

    // ---- Phase 3: reduce the 4 row phases, atomic into per-batch sum ----
    if (g == 0) {
        const float4 p0 = part[c];
        const float4 p1 = part[32 + c];
        const float4 p2 = part[64 + c];
        const float4 p3 = part[96 + c];
        float* dst = &g_sums[b * EMBED + c * 4];
        atomicAdd(dst + 0, p0.x + p1.x + p2.x + p3.x);
        atomicAdd(dst + 1, p0.y + p1.y + p2.y + p3.y);
        atomicAdd(dst + 2, p0.z + p1.z + p2.z + p3.z);
        atomicAdd(dst + 3, p0.w + p1.w + p2.w + p3.w);
    }

    __threadfence();
    __syncthreads();
    if (tid == 0) {
        const int old = atomicAdd(&g_count[b], 1);
        s_last = (old == NCHUNK - 1);
    }
    __syncthreads();

    // ---- Phase 4: last block of this batch finalizes ----
    // Output [B, 4, E], offsets [-1, -2, +1, +2]:
    //   off -1: S - emb[x[L-1]]               + 1*emb[0]
    //   off -2: S - emb[x[L-1]] - emb[x[L-2]] + 2*emb[0]
    //   off +1: S - emb[x[0]]                 + 1*emb[0]
    //   off +2: S - emb[x[0]]   - emb[x[1]]   + 2*emb[0]
    if (s_last) {
        const int e = tid;
        const float S = *(volatile float*)&g_sums[b * EMBED + e];

        long long tf0, tf1, tl0, tl1;
        if (is64) {
            const long long* x64 = (const long long*)xraw;
            tf0 = x64[(size_t)b * SEQLEN + 0];
            tf1 = x64[(size_t)b * SEQLEN + 1];
            tl1 = x64[(size_t)b * SEQLEN + (SEQLEN - 2)];
            tl0 = x64[(size_t)b * SEQLEN + (SEQLEN - 1)];
        } else {
            const int* x32 = (const int*)xraw;
            tf0 = x32[(size_t)b * SEQLEN + 0];
            tf1 = x32[(size_t)b * SEQLEN + 1];
            tl1 = x32[(size_t)b * SEQLEN + (SEQLEN - 2)];
            tl0 = x32[(size_t)b * SEQLEN + (SEQLEN - 1)];
        }
        if (tf0 < 0) tf0 = 0; if (tf0 >= VOCAB) tf0 = VOCAB - 1;
        if (tf1 < 0) tf1 = 0; if (tf1 >= VOCAB) tf1 = VOCAB - 1;
        if (tl0 < 0) tl0 = 0; if (tl0 >= VOCAB) tl0 = VOCAB - 1;
        if (tl1 < 0) tl1 = 0; if (tl1 >= VOCAB) tl1 = VOCAB - 1;

        const float e0 = emb[e];
        const float f0 = emb[(size_t)tf0 * EMBED + e];
        const float f1 = emb[(size_t)tf1 * EMBED + e];
        const float l0 = emb[(size_t)tl0 * EMBED + e];
        const float l1 = emb[(size_t)tl1 * EMBED + e];

        float* o = out + (size_t)b * 4 * EMBED;
        o[0 * EMBED + e] = S - l0 + e0;
        o[1 * EMBED + e] = S - l0 - l1 + 2.0f * e0;
        o[2 * EMBED + e] = S - f0 + e0;
        o[3 * EMBED + e] = S - f0 - f1 + 2.0f * e0;

        // Restore the zero-invariant for the next graph replay.
        g_sums[b * EMBED + e] = 0.0f;
        if (tid == 0) g_count[b] = 0;
    }
}

// ---------------------------------------------------------------------------
// Launch. Input order resolved from element counts:
//   x   : BATCH*SEQLEN = 131072 elements
//   emb : VOCAB*EMBED  = 12800000 elements
// ---------------------------------------------------------------------------
extern "C" void kernel_launch(void* const* d_in, const int* in_sizes, int n_in,
                              void* d_out, int out_size) {
    int ix = 0, ie = 1;
    if (in_sizes[0] != BATCH * SEQLEN) { ix = 1; ie = 0; }

    const void*  x   = d_in[ix];
    const float* emb = (const float*)d_in[ie];
    float*       out = (float*)d_out;

    dim3 grid(NCHUNK, BATCH);
    cbow_fused_kernel<<<grid, 128>>>(x, emb, out);
}